// round 1
// baseline (speedup 1.0000x reference)
#include <cuda_runtime.h>
#include <math.h>

#define N_NODES 2048
#define IN_F    128
#define OUT_F   32
#define NEG_INF (-9e15f)

// Kernel-2 tiling
#define KC      512        // k-chunk held in smem
#define ROWS    16         // rows (warps) per CTA
#define NSTEP   (KC / 32)

// Scratch (allocation-free rule: __device__ globals)
__device__ float g_Wh1[N_NODES * OUT_F];
__device__ float g_Wh2[N_NODES * OUT_F];
__device__ float g_c6[N_NODES];   // 0.6 * sum_f a_f * Wh1[i,f]
__device__ float g_dk6[N_NODES];  // 0.6 * sum_f a_f * Wh2[k,f]

// ---------------------------------------------------------------------------
// Kernel 1: Wh1 = h @ W[:128], Wh2 = h @ W[128:], plus row dot-products with a.
// CTA: (32 features, 8 rows). W cached in smem (32KB), h rows in smem (4KB).
// ---------------------------------------------------------------------------
__global__ __launch_bounds__(256) void gat_gemm_kernel(
    const float* __restrict__ h,
    const float* __restrict__ W,
    const float* __restrict__ a)
{
    __shared__ float Ws[2 * IN_F * OUT_F];  // 8192 floats = 32 KB
    __shared__ float hs[8][IN_F];           // 4 KB

    const int tx = threadIdx.x;            // feature 0..31
    const int ty = threadIdx.y;            // row-in-block 0..7
    const int tid = ty * 32 + tx;
    const int row0 = blockIdx.x * 8;

    // Cooperative loads (float4, coalesced)
    for (int i = tid; i < (2 * IN_F * OUT_F) / 4; i += 256)
        ((float4*)Ws)[i] = ((const float4*)W)[i];
    for (int i = tid; i < (8 * IN_F) / 4; i += 256)
        ((float4*)&hs[0][0])[i] = ((const float4*)(h + (size_t)row0 * IN_F))[i];
    __syncthreads();

    float wh1 = 0.f, wh2 = 0.f;
#pragma unroll 8
    for (int j = 0; j < IN_F; ++j) {
        float hv = hs[ty][j];                         // broadcast across lanes
        wh1 = fmaf(hv, Ws[j * OUT_F + tx], wh1);      // conflict-free
        wh2 = fmaf(hv, Ws[(IN_F + j) * OUT_F + tx], wh2);
    }

    const int row = row0 + ty;
    g_Wh1[row * OUT_F + tx] = wh1;
    g_Wh2[row * OUT_F + tx] = wh2;

    float av = a[tx];
    float c = av * wh1;
    float d = av * wh2;
#pragma unroll
    for (int off = 16; off; off >>= 1) {
        c += __shfl_xor_sync(0xffffffffu, c, off);
        d += __shfl_xor_sync(0xffffffffu, d, off);
    }
    if (tx == 0) {
        g_c6[row]  = 0.6f * c;
        g_dk6[row] = 0.6f * d;
    }
}

// ---------------------------------------------------------------------------
// Kernel 2: fused score + masked online-softmax + aggregation + ELU.
// One warp per output row; each lane owns k = lane, lane+32, ... (64 values).
// e[i,k] = c6_i + dk6_k + sum_f (0.4 a_f)|Wh1[i,f] + Wh2[k,f]|
// Smem tiles of Wh2/Wh1 are XOR-swizzled per float4 for conflict-free LDS.128.
// ---------------------------------------------------------------------------
extern __shared__ float smem2[];

__global__ __launch_bounds__(512, 1) void gat_attn_kernel(
    const int*   __restrict__ adj,
    const float* __restrict__ a,
    float*       __restrict__ out)
{
    float4* s_wh2 = (float4*)smem2;                      // KC*8 float4 (64 KB)
    float4* s_wh1 = (float4*)(smem2 + KC * OUT_F);       // KC*8 float4 (64 KB)
    float*  s_dk6 = smem2 + 2 * KC * OUT_F;              // KC floats  (2 KB)

    const int tid  = threadIdx.x;
    const int w    = tid >> 5;
    const int lane = tid & 31;
    const int row  = blockIdx.x * ROWS + w;

    // Per-lane register constants: a4[f] = 0.4*a[f], wh1i[f] = Wh1[row,f]
    float a4[OUT_F], wh1i[OUT_F], acc[OUT_F];
#pragma unroll
    for (int f = 0; f < OUT_F; ++f) {
        a4[f]   = 0.4f * __ldg(&a[f]);
        wh1i[f] = g_Wh1[row * OUT_F + f];
        acc[f]  = 0.f;
    }
    const float c6i = g_c6[row];

    float m = NEG_INF;      // running max (NEG_INF init reproduces masked-row semantics)
    float lsum = 0.f;       // running denominator

    const int* adj_row = adj + (size_t)row * N_NODES;
    int adj_next = adj_row[lane];                         // prefetch k = lane

    for (int kt = 0; kt < N_NODES; kt += KC) {
        __syncthreads();
        // Cooperative swizzled tile load (coalesced float4 from L2)
        for (int i = tid; i < KC * 8; i += 512) {
            int kk = i >> 3;
            int f4 = i & 7;
            int sidx = (kk << 3) | (f4 ^ (kk & 7));
            int gidx = ((kt + kk) << 3) | f4;
            s_wh2[sidx] = ((const float4*)g_Wh2)[gidx];
            s_wh1[sidx] = ((const float4*)g_Wh1)[gidx];
        }
        for (int i = tid; i < KC; i += 512) s_dk6[i] = g_dk6[kt + i];
        __syncthreads();

#pragma unroll 1
        for (int step = 0; step < NSTEP; ++step) {
            const int kk = (step << 5) | lane;            // index within tile
            const int adjv = adj_next;
            // one-ahead prefetch of adjacency (global k + 32), clamped at end
            int knext = kt + ((step + 1) << 5) + lane;
            if (knext >= N_NODES) knext = 0;
            adj_next = adj_row[knext];

            const int sbase = kk << 3;
            const int sx    = kk & 7;

            // Score: s2 = sum_f a4_f * |wh1i_f + wh2_kf|   (FADD + FFMA.|.| per f)
            float s2 = 0.f;
#pragma unroll
            for (int f4 = 0; f4 < 8; ++f4) {
                float4 v = s_wh2[sbase | (f4 ^ sx)];
                float x0 = wh1i[4 * f4 + 0] + v.x;
                float x1 = wh1i[4 * f4 + 1] + v.y;
                float x2 = wh1i[4 * f4 + 2] + v.z;
                float x3 = wh1i[4 * f4 + 3] + v.w;
                s2 = fmaf(a4[4 * f4 + 0], fabsf(x0), s2);
                s2 = fmaf(a4[4 * f4 + 1], fabsf(x1), s2);
                s2 = fmaf(a4[4 * f4 + 2], fabsf(x2), s2);
                s2 = fmaf(a4[4 * f4 + 3], fabsf(x3), s2);
            }
            const float e = (adjv > 0) ? (c6i + s_dk6[kk] + s2) : NEG_INF;

            // Branchless online softmax (per-lane state)
            const float mnew  = fmaxf(m, e);
            const float scale = __expf(m - mnew);   // 1.0 when m == mnew (incl. both NEG_INF)
            const float p     = __expf(e - mnew);
            m = mnew;
            lsum = fmaf(lsum, scale, p);

            // Aggregate p * Wh1[k,:] with rescale folded into one FFMA per f
#pragma unroll
            for (int f4 = 0; f4 < 8; ++f4) {
                float4 v = s_wh1[sbase | (f4 ^ sx)];
                acc[4 * f4 + 0] = fmaf(acc[4 * f4 + 0], scale, p * v.x);
                acc[4 * f4 + 1] = fmaf(acc[4 * f4 + 1], scale, p * v.y);
                acc[4 * f4 + 2] = fmaf(acc[4 * f4 + 2], scale, p * v.z);
                acc[4 * f4 + 3] = fmaf(acc[4 * f4 + 3], scale, p * v.w);
            }
        }
    }

    // ---- Cross-lane combine ----
    float mg = m;
#pragma unroll
    for (int off = 16; off; off >>= 1)
        mg = fmaxf(mg, __shfl_xor_sync(0xffffffffu, mg, off));
    const float cs = __expf(m - mg);
    float L = lsum * cs;
#pragma unroll
    for (int off = 16; off; off >>= 1)
        L += __shfl_xor_sync(0xffffffffu, L, off);

    __syncthreads();  // tiles no longer needed by any warp -> reuse smem
    float* red = smem2 + w * (32 * 33);   // 16 warps * 4224 B = 67.6 KB < 130 KB
#pragma unroll
    for (int f = 0; f < OUT_F; ++f)
        red[lane * 33 + f] = acc[f] * cs;
    __syncwarp();

    float tot = 0.f;
#pragma unroll 8
    for (int j = 0; j < 32; ++j)
        tot += red[j * 33 + lane];        // conflict-free (pad 33)

    const float hv = tot / L;
    out[row * OUT_F + lane] = hv > 0.f ? hv : expm1f(hv);  // ELU
}

// ---------------------------------------------------------------------------
// Launch
// ---------------------------------------------------------------------------
extern "C" void kernel_launch(void* const* d_in, const int* in_sizes, int n_in,
                              void* d_out, int out_size)
{
    const float* h   = (const float*)d_in[0];   // [2048,128] f32
    const int*   adj = (const int*)  d_in[1];   // [2048,2048] i32
    const float* W   = (const float*)d_in[2];   // [256,32] f32
    const float* a   = (const float*)d_in[3];   // [32] f32
    float*       out = (float*)d_out;           // [2048,32] f32

    gat_gemm_kernel<<<N_NODES / 8, dim3(32, 8)>>>(h, W, a);

    const int smem_bytes = (2 * KC * OUT_F + KC) * (int)sizeof(float);  // 133120
    static int attr_set = 0;
    cudaFuncSetAttribute(gat_attn_kernel,
                         cudaFuncAttributeMaxDynamicSharedMemorySize, smem_bytes);
    (void)attr_set;
    gat_attn_kernel<<<N_NODES / ROWS, 512, smem_bytes>>>(adj, a, out);
}